// round 2
// baseline (speedup 1.0000x reference)
#include <cuda_runtime.h>
#include <math.h>

#define B_    16
#define T_    2048
#define NQ_   1024
#define DH_   128
#define NK_   8192   // T_*4 keys per batch

// ---------------- scratch (device globals; no runtime allocs) ----------------
__device__ float g_qb[NQ_ * DH_];              // projected (pre-rotary) queries
__device__ float g_k[(size_t)B_ * NK_ * DH_];  // compacted rotated K
__device__ float g_v[(size_t)B_ * NK_ * DH_];  // compacted rotated V
__device__ float g_wkvT[256 * 256];            // w_kv transposed [k][j]
__device__ int   g_validr[B_ * T_];            // valid mask positions per batch
__device__ int   g_nvalid[B_];
__device__ float g_part[B_ * 16 * DH_];        // per (b, q-tile) partial output sums

// ---------------- prep: mask compaction (+ dtype detect) and w_kv transpose ----------------
__global__ void k_prep(const void* __restrict__ mask_raw, const float* __restrict__ w_kv) {
    int bid = blockIdx.x;
    int tid = threadIdx.x;
    if (bid == B_) {
        // transpose w_kv (256x256): g_wkvT[k*256+j] = w_kv[j*256+k]
        for (int e = tid; e < 256 * 256; e += 256) {
            int j = e >> 8, k = e & 255;
            g_wkvT[k * 256 + j] = w_kv[j * 256 + k];
        }
        return;
    }
    __shared__ int s_f0, s_fr;
    __shared__ int s_wsum[8];
    __shared__ int s_woff[8];
    if (tid == 0) { s_f0 = 0; s_fr = 0; }
    __syncthreads();
    // dtype detection on first 4096 bytes:
    //   int32 1  -> bytes [1,0,0,0] : off0 nonzero, rest zero
    //   bool  1  -> byte  [1]       : off0 nonzero, rest nonzero (other elements)
    //   float 1. -> bytes [0,0,0x80,0x3f] : off0 zero, rest nonzero
    const unsigned char* mb = (const unsigned char*)mask_raw;
    int a0 = 0, ar = 0;
    for (int i = tid * 16; i < tid * 16 + 16; i++) {
        unsigned char v = mb[i];
        if (v) { if ((i & 3) == 0) a0 = 1; else ar = 1; }
    }
    if (a0) atomicOr(&s_f0, 1);
    if (ar) atomicOr(&s_fr, 1);
    __syncthreads();
    int mode = (!s_f0) ? 2 : (s_fr ? 1 : 0);  // 2=float32, 1=bool, 0=int32
    const int*   mi = (const int*)mask_raw;
    const float* mf = (const float*)mask_raw;

    int pred[8];
    int c = 0;
#pragma unroll
    for (int j = 0; j < 8; j++) {
        int r = tid * 8 + j;
        int m;
        if (mode == 1)      m = (mb[bid * T_ + r] != 0);
        else if (mode == 0) m = (mi[bid * T_ + r] != 0);
        else                m = (mf[bid * T_ + r] != 0.0f);
        pred[j] = m;
        c += m;
    }
    int lane = tid & 31, wid = tid >> 5;
    int inc = c;
#pragma unroll
    for (int off = 1; off < 32; off <<= 1) {
        int n = __shfl_up_sync(0xffffffffu, inc, off);
        if (lane >= off) inc += n;
    }
    if (lane == 31) s_wsum[wid] = inc;
    __syncthreads();
    if (tid == 0) {
        int run = 0;
        for (int w = 0; w < 8; w++) { s_woff[w] = run; run += s_wsum[w]; }
        g_nvalid[bid] = run;
    }
    __syncthreads();
    int pos = s_woff[wid] + inc - c;
#pragma unroll
    for (int j = 0; j < 8; j++)
        if (pred[j]) g_validr[bid * T_ + pos++] = tid * 8 + j;
}

// ---------------- Q path: LN(x_query) @ w_q^T -> g_qb (1024x128) ----------------
__global__ void k_q(const float* __restrict__ xq, const float* __restrict__ lnw,
                    const float* __restrict__ lnb, const float* __restrict__ wq) {
    __shared__ float sXN[8 * 512];
    int tid = threadIdx.x, lane = tid & 31, wid = tid >> 5;
    int q = blockIdx.x * 8 + wid;
    const float* row = xq + q * 512;
    float v[16], sum = 0.f, sq = 0.f;
#pragma unroll
    for (int i = 0; i < 16; i++) {
        float x = row[lane + 32 * i];
        v[i] = x; sum += x; sq += x * x;
    }
#pragma unroll
    for (int o = 16; o > 0; o >>= 1) {
        sum += __shfl_xor_sync(0xffffffffu, sum, o);
        sq  += __shfl_xor_sync(0xffffffffu, sq, o);
    }
    float mu = sum * (1.f / 512.f);
    float var = sq * (1.f / 512.f) - mu * mu;
    float rs = rsqrtf(var + 1e-5f);
#pragma unroll
    for (int i = 0; i < 16; i++) {
        int k = lane + 32 * i;
        sXN[wid * 512 + k] = (v[i] - mu) * rs * lnw[k] + lnb[k];
    }
    __syncthreads();
#pragma unroll
    for (int it = 0; it < 4; it++) {
        int idx = tid + 256 * it;
        int qq = idx >> 7, d = idx & 127;
        const float4* xr = (const float4*)(sXN + qq * 512);
        const float4* wr = (const float4*)(wq + d * 512);
        float acc = 0.f;
#pragma unroll 8
        for (int k4 = 0; k4 < 128; k4++) {
            float4 a = xr[k4], w = wr[k4];
            acc += a.x * w.x + a.y * w.y + a.z * w.z + a.w * w.w;
        }
        g_qb[(blockIdx.x * 8 + qq) * 128 + d] = acc;
    }
}

// ---------------- KV path: LN(x_context) @ w_kv^T + rotary, compacted ----------------
// block: 16 valid positions r -> 64 rows (4 tile-copies g, key p = 2048*g + r,
// context element t = 512*g + r/4, c = r%4)
__global__ void __launch_bounds__(256, 2)
k_kv(const float* __restrict__ xc, const float* __restrict__ lnw,
     const float* __restrict__ lnb, const float* __restrict__ rotc) {
    extern __shared__ float smem[];
    float* sXN = smem;              // 64*256 (later reused for kv results)
    float* sW  = smem + 64 * 256;   // 32*256
    __shared__ int s_r[16];

    int b = blockIdx.y;
    int vi0 = blockIdx.x * 16;
    int nv = g_nvalid[b];
    if (vi0 >= nv) return;
    int cnt = min(16, nv - vi0);
    int nrows = cnt * 4;
    int tid = threadIdx.x, lane = tid & 31, wid = tid >> 5;
    if (tid < 16) s_r[tid] = (tid < cnt) ? g_validr[b * T_ + vi0 + tid] : 0;
    __syncthreads();

    // LayerNorm: 64 rows of 256
    for (int rl = wid; rl < 64; rl += 8) {
        if (rl < nrows) {
            int vl = rl >> 2, g = rl & 3;
            int r = s_r[vl];
            int t = 512 * g + (r >> 2), cc = r & 3;
            const float* row = xc + (((size_t)b * T_ + t) * 4 + cc) * 256;
            float v[8], sum = 0.f, sq = 0.f;
#pragma unroll
            for (int i = 0; i < 8; i++) {
                float x = row[lane + 32 * i];
                v[i] = x; sum += x; sq += x * x;
            }
#pragma unroll
            for (int o = 16; o > 0; o >>= 1) {
                sum += __shfl_xor_sync(0xffffffffu, sum, o);
                sq  += __shfl_xor_sync(0xffffffffu, sq, o);
            }
            float mu = sum * (1.f / 256.f);
            float var = sq * (1.f / 256.f) - mu * mu;
            float rs = rsqrtf(var + 1e-5f);
#pragma unroll
            for (int i = 0; i < 8; i++) {
                int k = lane + 32 * i;
                sXN[rl * 256 + k] = (v[i] - mu) * rs * lnw[k] + lnb[k];
            }
        }
    }
    __syncthreads();

    // GEMM: 64 rows x 256 outs, K=256 (thread: 4 rows x 16 cols, cols tx+16u)
    int ty = tid >> 4, tx = tid & 15;
    float acc[4][16];
#pragma unroll
    for (int i = 0; i < 4; i++)
#pragma unroll
        for (int u = 0; u < 16; u++) acc[i][u] = 0.f;

    for (int k0 = 0; k0 < 256; k0 += 32) {
        float4* dst = (float4*)sW;
        const float4* src = (const float4*)(g_wkvT + k0 * 256);
        for (int e = tid; e < 2048; e += 256) dst[e] = src[e];
        __syncthreads();
#pragma unroll 4
        for (int kk = 0; kk < 32; kk++) {
            float x0 = sXN[(ty * 4 + 0) * 256 + k0 + kk];
            float x1 = sXN[(ty * 4 + 1) * 256 + k0 + kk];
            float x2 = sXN[(ty * 4 + 2) * 256 + k0 + kk];
            float x3 = sXN[(ty * 4 + 3) * 256 + k0 + kk];
            const float* wrow = sW + kk * 256 + tx;
#pragma unroll
            for (int u = 0; u < 16; u++) {
                float w = wrow[16 * u];
                acc[0][u] += x0 * w;
                acc[1][u] += x1 * w;
                acc[2][u] += x2 * w;
                acc[3][u] += x3 * w;
            }
        }
        __syncthreads();
    }

    // stash kv in sXN (reuse), then rotary + write to compacted g_k/g_v
#pragma unroll
    for (int i = 0; i < 4; i++)
#pragma unroll
        for (int u = 0; u < 16; u++)
            sXN[(ty * 4 + i) * 256 + tx + 16 * u] = acc[i][u];
    __syncthreads();

    for (int pe = tid; pe < 64 * 128; pe += 256) {
        int rl = pe >> 7, m = pe & 127;
        if (rl >= nrows) continue;
        int j0 = m * 2;
        float a  = sXN[rl * 256 + j0];
        float bb = sXN[rl * 256 + j0 + 1];
        int vl = rl >> 2, g = rl & 3;
        int r = s_r[vl];
        int p = 2048 * g + r;            // original key position (freq index)
        int d0 = j0 & 127;               // dim within k-half or v-half
        const float* f = rotc + ((size_t)b * NK_ + p) * 128 + d0;
        float s0, c0, s1, c1;
        __sincosf(f[0], &s0, &c0);
        __sincosf(f[1], &s1, &c1);
        float y0 = a * c0 - bb * s0;
        float y1 = bb * c1 + a * s1;
        int ck = (vi0 + vl) * 4 + g;     // compacted key index
        float* dstp = (m < 64 ? g_k : g_v) + ((size_t)b * NK_ + ck) * 128 + d0;
        dstp[0] = y0;
        dstp[1] = y1;
    }
}

// ---------------- flash attention over compacted keys + inverse rotary + q-sum ----------------
// block = (q-tile of 64, batch). smem: QT[128x68], KV (K as [d][r] 128x68 / V as [r][d] 64x132),
// S [64x68], m/l/corr [64].
__global__ void __launch_bounds__(256, 2)
k_flash(const float* __restrict__ rotq) {
    extern __shared__ float sm[];
    float* sQT = sm;                 // 128 x 68 (transposed Q, rotated+scaled)
    float* sKV = sm + 8704;          // K: [d*68+r] ; V: [r*132+d]
    float* sS  = sm + 17408;         // 64 x 68
    float* sM  = sm + 17408 + 4352;
    float* sL  = sM + 64;
    float* sC  = sL + 64;

    int tid = threadIdx.x;
    int tx = tid & 15, ty = tid >> 4;
    int qt = blockIdx.x, b = blockIdx.y;
    int q0 = qt * 64;
    int nkeys = g_nvalid[b] * 4;
    const float scale = 0.08838834764831845f;  // 1/sqrt(128)

    // load + rotate + scale Q, store transposed
    for (int e = tid; e < 64 * 32; e += 256) {
        int r = e & 63, d4 = e >> 6;
        float4 qv = *(const float4*)(g_qb + (q0 + r) * 128 + d4 * 4);
        float4 fv = *(const float4*)(rotq + ((size_t)b * NQ_ + q0 + r) * 128 + d4 * 4);
        float s0, c0, s1, c1, s2, c2, s3, c3;
        __sincosf(fv.x, &s0, &c0); __sincosf(fv.y, &s1, &c1);
        __sincosf(fv.z, &s2, &c2); __sincosf(fv.w, &s3, &c3);
        sQT[(4 * d4 + 0) * 68 + r] = (qv.x * c0 - qv.y * s0) * scale;
        sQT[(4 * d4 + 1) * 68 + r] = (qv.y * c1 + qv.x * s1) * scale;
        sQT[(4 * d4 + 2) * 68 + r] = (qv.z * c2 - qv.w * s2) * scale;
        sQT[(4 * d4 + 3) * 68 + r] = (qv.w * c3 + qv.z * s3) * scale;
    }
    if (tid < 64) { sM[tid] = -1e30f; sL[tid] = 0.f; }

    float acc[4][8];
#pragma unroll
    for (int i = 0; i < 4; i++)
#pragma unroll
        for (int u = 0; u < 8; u++) acc[i][u] = 0.f;

    int ntiles = (nkeys + 63) >> 6;
    for (int kt = 0; kt < ntiles; kt++) {
        int k0 = kt << 6;
        __syncthreads();  // prev PV done / Q ready
        // K tile, transposed [d][r]
        for (int e = tid; e < 2048; e += 256) {
            int r = e & 63, d4 = e >> 6;
            float4 kv = (k0 + r < nkeys)
                ? *(const float4*)(g_k + ((size_t)b * NK_ + k0 + r) * 128 + d4 * 4)
                : make_float4(0.f, 0.f, 0.f, 0.f);
            sKV[(4 * d4 + 0) * 68 + r] = kv.x;
            sKV[(4 * d4 + 1) * 68 + r] = kv.y;
            sKV[(4 * d4 + 2) * 68 + r] = kv.z;
            sKV[(4 * d4 + 3) * 68 + r] = kv.w;
        }
        __syncthreads();

        // S = Q K^T : 4x4 micro-tile via outer products
        float s[4][4];
#pragma unroll
        for (int i = 0; i < 4; i++)
#pragma unroll
            for (int j = 0; j < 4; j++) s[i][j] = 0.f;
#pragma unroll 4
        for (int d = 0; d < 128; d++) {
            float4 a  = *(const float4*)(sQT + d * 68 + ty * 4);
            float4 bb = *(const float4*)(sKV + d * 68 + tx * 4);
            s[0][0] += a.x * bb.x; s[0][1] += a.x * bb.y; s[0][2] += a.x * bb.z; s[0][3] += a.x * bb.w;
            s[1][0] += a.y * bb.x; s[1][1] += a.y * bb.y; s[1][2] += a.y * bb.z; s[1][3] += a.y * bb.w;
            s[2][0] += a.z * bb.x; s[2][1] += a.z * bb.y; s[2][2] += a.z * bb.z; s[2][3] += a.z * bb.w;
            s[3][0] += a.w * bb.x; s[3][1] += a.w * bb.y; s[3][2] += a.w * bb.z; s[3][3] += a.w * bb.w;
        }
#pragma unroll
        for (int i = 0; i < 4; i++)
#pragma unroll
            for (int j = 0; j < 4; j++) {
                int kk = tx * 4 + j;
                sS[(ty * 4 + i) * 68 + kk] = (k0 + kk < nkeys) ? s[i][j] : -1e30f;
            }
        __syncthreads();

        // V tile (row layout), then online softmax on sS
        for (int e = tid; e < 2048; e += 256) {
            int r = e & 63, d4 = e >> 6;
            float4 vv = (k0 + r < nkeys)
                ? *(const float4*)(g_v + ((size_t)b * NK_ + k0 + r) * 128 + d4 * 4)
                : make_float4(0.f, 0.f, 0.f, 0.f);
            *(float4*)(sKV + r * 132 + d4 * 4) = vv;
        }
        {
            int r = tid >> 2, qq = tid & 3;
            float* rowp = sS + r * 68 + qq * 16;
            float mold = sM[r];
            float mloc = -1e30f;
#pragma unroll
            for (int c = 0; c < 16; c++) mloc = fmaxf(mloc, rowp[c]);
            mloc = fmaxf(mloc, __shfl_xor_sync(0xffffffffu, mloc, 1));
            mloc = fmaxf(mloc, __shfl_xor_sync(0xffffffffu, mloc, 2));
            float mnew = fmaxf(mold, mloc);
            float lsum = 0.f;
#pragma unroll
            for (int c = 0; c < 16; c++) {
                float p = __expf(rowp[c] - mnew);
                rowp[c] = p;
                lsum += p;
            }
            lsum += __shfl_xor_sync(0xffffffffu, lsum, 1);
            lsum += __shfl_xor_sync(0xffffffffu, lsum, 2);
            if (qq == 0) {
                float corr = __expf(mold - mnew);
                sC[r] = corr;
                sL[r] = sL[r] * corr + lsum;
                sM[r] = mnew;
            }
        }
        __syncthreads();

        // rescale + PV (4 rows x 8 cols per thread)
        float cr0 = sC[ty * 4 + 0], cr1 = sC[ty * 4 + 1];
        float cr2 = sC[ty * 4 + 2], cr3 = sC[ty * 4 + 3];
#pragma unroll
        for (int u = 0; u < 8; u++) {
            acc[0][u] *= cr0; acc[1][u] *= cr1; acc[2][u] *= cr2; acc[3][u] *= cr3;
        }
#pragma unroll 4
        for (int k = 0; k < 64; k++) {
            float p0 = sS[(ty * 4 + 0) * 68 + k];
            float p1 = sS[(ty * 4 + 1) * 68 + k];
            float p2 = sS[(ty * 4 + 2) * 68 + k];
            float p3 = sS[(ty * 4 + 3) * 68 + k];
            float4 v0 = *(const float4*)(sKV + k * 132 + tx * 8);
            float4 v1 = *(const float4*)(sKV + k * 132 + tx * 8 + 4);
            acc[0][0] += p0 * v0.x; acc[0][1] += p0 * v0.y; acc[0][2] += p0 * v0.z; acc[0][3] += p0 * v0.w;
            acc[0][4] += p0 * v1.x; acc[0][5] += p0 * v1.y; acc[0][6] += p0 * v1.z; acc[0][7] += p0 * v1.w;
            acc[1][0] += p1 * v0.x; acc[1][1] += p1 * v0.y; acc[1][2] += p1 * v0.z; acc[1][3] += p1 * v0.w;
            acc[1][4] += p1 * v1.x; acc[1][5] += p1 * v1.y; acc[1][6] += p1 * v1.z; acc[1][7] += p1 * v1.w;
            acc[2][0] += p2 * v0.x; acc[2][1] += p2 * v0.y; acc[2][2] += p2 * v0.z; acc[2][3] += p2 * v0.w;
            acc[2][4] += p2 * v1.x; acc[2][5] += p2 * v1.y; acc[2][6] += p2 * v1.z; acc[2][7] += p2 * v1.w;
            acc[3][0] += p3 * v0.x; acc[3][1] += p3 * v0.y; acc[3][2] += p3 * v0.z; acc[3][3] += p3 * v0.w;
            acc[3][4] += p3 * v1.x; acc[3][5] += p3 * v1.y; acc[3][6] += p3 * v1.z; acc[3][7] += p3 * v1.w;
        }
    }
    __syncthreads();

    // normalize, inverse rotary (cos f, -sin f), partial sum over own 4 rows
    float out8[8];
#pragma unroll
    for (int u = 0; u < 8; u++) out8[u] = 0.f;
#pragma unroll
    for (int i = 0; i < 4; i++) {
        int r = ty * 4 + i;
        float lv = sL[r];
        float linv = (lv > 0.f) ? (1.f / lv) : 0.f;
        const float* f = rotq + ((size_t)b * NQ_ + q0 + r) * 128 + tx * 8;
#pragma unroll
        for (int u = 0; u < 8; u += 2) {
            float a  = acc[i][u]     * linv;
            float bb = acc[i][u + 1] * linv;
            float s0, c0, s1, c1;
            __sincosf(f[u],     &s0, &c0);
            __sincosf(f[u + 1], &s1, &c1);
            out8[u]     += a * c0 + bb * s0;
            out8[u + 1] += bb * c1 - a * s1;
        }
    }
    // reduce over the 16 ty groups (reuse sS as 16x128)
    float* sRed = sS;
#pragma unroll
    for (int u = 0; u < 8; u++) sRed[ty * 128 + tx * 8 + u] = out8[u];
    __syncthreads();
    if (tid < 128) {
        float sum = 0.f;
#pragma unroll
        for (int t = 0; t < 16; t++) sum += sRed[t * 128 + tid];
        g_part[((size_t)b * 16 + qt) * 128 + tid] = sum;
    }
}

// ---------------- final: mean over queries + projection ----------------
__global__ void k_out(const float* __restrict__ w_o, const float* __restrict__ b_o,
                      float* __restrict__ out) {
    __shared__ float mean[128];
    int b = blockIdx.x, tid = threadIdx.x;
    if (tid < 128) {
        float s = 0.f;
#pragma unroll
        for (int qt2 = 0; qt2 < 16; qt2++) s += g_part[((size_t)b * 16 + qt2) * 128 + tid];
        mean[tid] = s * (1.f / 1024.f);
    }
    __syncthreads();
    for (int o = tid; o < 512; o += 256) {
        const float4* wr = (const float4*)(w_o + o * 128);
        float acc = 0.f;
#pragma unroll
        for (int d4 = 0; d4 < 32; d4++) {
            float4 w = wr[d4];
            acc += w.x * mean[d4 * 4] + w.y * mean[d4 * 4 + 1]
                 + w.z * mean[d4 * 4 + 2] + w.w * mean[d4 * 4 + 3];
        }
        out[b * 512 + o] = acc + b_o[o];
    }
}

extern "C" void kernel_launch(void* const* d_in, const int* in_sizes, int n_in,
                              void* d_out, int out_size) {
    const float* xq   = (const float*)d_in[0];
    const float* xc   = (const float*)d_in[1];
    const float* rotq = (const float*)d_in[2];
    const float* rotc = (const float*)d_in[3];
    const void*  mask = d_in[4];
    const float* lnqw = (const float*)d_in[5];
    const float* lnqb = (const float*)d_in[6];
    const float* lncw = (const float*)d_in[7];
    const float* lncb = (const float*)d_in[8];
    const float* wq   = (const float*)d_in[9];
    const float* wkv  = (const float*)d_in[10];
    const float* wo   = (const float*)d_in[11];
    const float* bo   = (const float*)d_in[12];
    float* out = (float*)d_out;

    cudaFuncSetAttribute(k_kv,    cudaFuncAttributeMaxDynamicSharedMemorySize, 98304);
    cudaFuncSetAttribute(k_flash, cudaFuncAttributeMaxDynamicSharedMemorySize, 88064);

    k_prep<<<B_ + 1, 256>>>(mask, wkv);
    k_q<<<128, 256>>>(xq, lnqw, lnqb, wq);
    k_kv<<<dim3(128, B_), 256, 98304>>>(xc, lncw, lncb, rotc);
    k_flash<<<dim3(16, B_), 256, 87808>>>(rotq);
    k_out<<<B_, 256>>>(wo, bo, out);
}